// round 12
// baseline (speedup 1.0000x reference)
#include <cuda_runtime.h>
#include <cuda_fp16.h>
#include <math.h>
#include <stdint.h>

#define B_   8
#define NTOK 512
#define NCTX 2048
#define EMBD 512
#define HH   8
#define DKV  64

#define OUT_ELEMS ((size_t)B_ * NTOK * EMBD)

// ---------------- scratch -----------------------------------------------------
__device__ __half g_xq[B_ * NTOK * EMBD];
__device__ __half g_xk[B_ * NCTX * EMBD];
__device__ __half g_xv[B_ * NCTX * EMBD];
__device__ __half g_wat[EMBD * EMBD], g_wac[EMBD * EMBD], g_wbc[EMBD * EMBD], g_wr[EMBD * EMBD];
__device__ __half g_q [B_ * HH * NTOK * DKV];   // normalized q-hat
__device__ __half g_k [B_ * HH * NCTX * DKV];   // normalized k-hat
__device__ __half g_v [B_ * HH * NCTX * DKV];
__device__ __half g_ho[B_ * NTOK * HH * DKV];

// ---------------- ptx helpers -------------------------------------------------
__device__ __forceinline__ void cp16(uint32_t dst, const void* src) {
    asm volatile("cp.async.cg.shared.global [%0], [%1], 16;" :: "r"(dst), "l"(src));
}
#define CP_COMMIT() asm volatile("cp.async.commit_group;" ::: "memory")
template <int N> __device__ __forceinline__ void cp_wait() {
    asm volatile("cp.async.wait_group %0;" :: "n"(N) : "memory");
}
__device__ __forceinline__ void ldsm4(uint32_t* d, uint32_t addr) {
    asm volatile("ldmatrix.sync.aligned.m8n8.x4.shared.b16 {%0,%1,%2,%3}, [%4];"
        : "=r"(d[0]), "=r"(d[1]), "=r"(d[2]), "=r"(d[3]) : "r"(addr));
}
__device__ __forceinline__ void ldsm4t(uint32_t* d, uint32_t addr) {
    asm volatile("ldmatrix.sync.aligned.m8n8.x4.trans.shared.b16 {%0,%1,%2,%3}, [%4];"
        : "=r"(d[0]), "=r"(d[1]), "=r"(d[2]), "=r"(d[3]) : "r"(addr));
}
__device__ __forceinline__ void mma16(float* c, const uint32_t* a, const uint32_t* b) {
    asm volatile(
        "mma.sync.aligned.m16n8k16.row.col.f32.f16.f16.f32 "
        "{%0,%1,%2,%3}, {%4,%5,%6,%7}, {%8,%9}, {%0,%1,%2,%3};"
        : "+f"(c[0]), "+f"(c[1]), "+f"(c[2]), "+f"(c[3])
        : "r"(a[0]), "r"(a[1]), "r"(a[2]), "r"(a[3]), "r"(b[0]), "r"(b[1]));
}
// exp(x) for |x| <= ~1.0: degree-8 Taylor, 9 FFMA, abs err < 1e-5
__device__ __forceinline__ float exp_c(float x)
{
    float p = 2.48015873e-5f;
    p = fmaf(p, x, 1.98412698e-4f);
    p = fmaf(p, x, 1.38888889e-3f);
    p = fmaf(p, x, 8.33333333e-3f);
    p = fmaf(p, x, 4.16666667e-2f);
    p = fmaf(p, x, 0.16666667f);
    p = fmaf(p, x, 0.5f);
    p = fmaf(p, x, 1.0f);
    p = fmaf(p, x, 1.0f);
    return p;
}

// ---------------- fused fp32 -> fp16 convert (all 7 tensors) ------------------
// 2048 floats per block. q:1024 blocks, k:4096, v:4096, each weight:128 -> 9728.
__global__ __launch_bounds__(256) void cvt_all(
    const float* __restrict__ q, const float* __restrict__ k, const float* __restrict__ v,
    const float* __restrict__ wat, const float* __restrict__ wac,
    const float* __restrict__ wbc, const float* __restrict__ wr)
{
    int bid = blockIdx.x;
    const float* s; __half* d; int off;
    if      (bid < 1024) { s = q;   d = g_xq;  off = bid;        }
    else if (bid < 5120) { s = k;   d = g_xk;  off = bid - 1024; }
    else if (bid < 9216) { s = v;   d = g_xv;  off = bid - 5120; }
    else if (bid < 9344) { s = wat; d = g_wat; off = bid - 9216; }
    else if (bid < 9472) { s = wac; d = g_wac; off = bid - 9344; }
    else if (bid < 9600) { s = wbc; d = g_wbc; off = bid - 9472; }
    else                 { s = wr;  d = g_wr;  off = bid - 9600; }
    size_t i = (size_t)off * 2048 + threadIdx.x * 8;
    float4 a = *(const float4*)(s + i);
    float4 b = *(const float4*)(s + i + 4);
    __half2 h0 = __floats2half2_rn(a.x, a.y), h1 = __floats2half2_rn(a.z, a.w);
    __half2 h2 = __floats2half2_rn(b.x, b.y), h3 = __floats2half2_rn(b.z, b.w);
    uint4 o;
    o.x = *(uint32_t*)&h0; o.y = *(uint32_t*)&h1;
    o.z = *(uint32_t*)&h2; o.w = *(uint32_t*)&h3;
    *(uint4*)(d + i) = o;
}

// ---------------- fp16 NT GEMM (cp.async 4-stage) -----------------------------
// MODE 0: float C[m*N+n] = acc + bias
// MODE 1: half head scatter; NORMALIZE: scale each head-row to unit L2 norm
#define SA 40
#define GS_A 5120
template <int MODE, bool NORMALIZE>
__global__ __launch_bounds__(256, 2) void gemm_f16(
    const __half* __restrict__ A, const __half* __restrict__ Bm,
    const float* __restrict__ bias, void* __restrict__ Cv,
    int M, int N, int K, int ntok)
{
    extern __shared__ __half smg[];
    const uint32_t base = (uint32_t)__cvta_generic_to_shared(smg);

    const int tid  = threadIdx.x;
    const int wid  = tid >> 5;
    const int lane = tid & 31;
    const int r    = lane >> 2;
    const int cq   = lane & 3;
    const int wm   = wid & 3;
    const int wn   = wid >> 2;
    const int row0 = blockIdx.y * 128;
    const int col0 = blockIdx.x * 128;

    const int lr  = lane & 7, grp = lane >> 3;
    const int aRO = ((grp & 1) << 3) + lr, aKO = (grp >> 1) << 3;
    const int bRO = ((grp >> 1) << 3) + lr, bKO = (grp & 1) << 3;

    const int crow = tid >> 2;
    const int cseg = (tid & 3) * 8;

    auto issue = [&](int s) {
        int st = s & 3, k0 = s * 32;
        uint32_t dA = base + (st * GS_A) * 2;
        uint32_t dB = base + ((4 + st) * GS_A) * 2;
#pragma unroll
        for (int i = 0; i < 2; i++) {
            int row = crow + i * 64;
            cp16(dA + (row * SA + cseg) * 2, A  + (size_t)(row0 + row) * K + k0 + cseg);
            cp16(dB + (row * SA + cseg) * 2, Bm + (size_t)(col0 + row) * K + k0 + cseg);
        }
    };

    float cr[2][8][4];
#pragma unroll
    for (int mt = 0; mt < 2; mt++)
#pragma unroll
        for (int nt = 0; nt < 8; nt++)
#pragma unroll
            for (int e = 0; e < 4; e++) cr[mt][nt][e] = 0.f;

    const int S = K >> 5;
    issue(0); CP_COMMIT();
    issue(1); CP_COMMIT();
    issue(2); CP_COMMIT();

    for (int s = 0; s < S; s++) {
        cp_wait<2>();
        __syncthreads();
        if (s + 3 < S) { issue(s + 3); CP_COMMIT(); }

        const int st = s & 3;
        const uint32_t aO = base + (st * GS_A) * 2;
        const uint32_t bO = base + ((4 + st) * GS_A) * 2;
#pragma unroll
        for (int k16 = 0; k16 < 2; k16++) {
            uint32_t af[2][4];
#pragma unroll
            for (int mt = 0; mt < 2; mt++)
                ldsm4(af[mt], aO + ((wm * 32 + mt * 16 + aRO) * SA + k16 * 16 + aKO) * 2);
            uint32_t bf[8][2];
#pragma unroll
            for (int ntp = 0; ntp < 4; ntp++) {
                uint32_t t[4];
                ldsm4(t, bO + ((wn * 64 + ntp * 16 + bRO) * SA + k16 * 16 + bKO) * 2);
                bf[2 * ntp][0] = t[0]; bf[2 * ntp][1] = t[1];
                bf[2 * ntp + 1][0] = t[2]; bf[2 * ntp + 1][1] = t[3];
            }
#pragma unroll
            for (int mt = 0; mt < 2; mt++)
#pragma unroll
                for (int nt = 0; nt < 8; nt++)
                    mma16(cr[mt][nt], af[mt], bf[nt]);
        }
        __syncthreads();
    }

    // -------- epilogue --------------------------------------------------------
#pragma unroll
    for (int mt = 0; mt < 2; mt++) {
        const int m1 = row0 + wm * 32 + mt * 16 + r;
        const int m2 = m1 + 8;
        float inv1 = 1.f, inv2 = 1.f;

        if (NORMALIZE) {
            float ss1 = 0.f, ss2 = 0.f;
#pragma unroll
            for (int nt = 0; nt < 8; nt++) {
                const int n = col0 + wn * 64 + nt * 8 + 2 * cq;
                float* cc = cr[mt][nt];
                float bx = bias[n], by = bias[n + 1];
                cc[0] += bx; cc[1] += by; cc[2] += bx; cc[3] += by;
                ss1 = fmaf(cc[0], cc[0], fmaf(cc[1], cc[1], ss1));
                ss2 = fmaf(cc[2], cc[2], fmaf(cc[3], cc[3], ss2));
            }
            ss1 += __shfl_xor_sync(0xffffffffu, ss1, 1);
            ss1 += __shfl_xor_sync(0xffffffffu, ss1, 2);
            ss2 += __shfl_xor_sync(0xffffffffu, ss2, 1);
            ss2 += __shfl_xor_sync(0xffffffffu, ss2, 2);
            inv1 = rsqrtf(fmaxf(ss1, 1e-30f));
            inv2 = rsqrtf(fmaxf(ss2, 1e-30f));
        }

#pragma unroll
        for (int nt = 0; nt < 8; nt++) {
            const int n = col0 + wn * 64 + nt * 8 + 2 * cq;
            float* cc = cr[mt][nt];
            float v1x, v1y, v2x, v2y;
            if (NORMALIZE) {
                v1x = cc[0] * inv1; v1y = cc[1] * inv1;
                v2x = cc[2] * inv2; v2y = cc[3] * inv2;
            } else {
                float bx = bias[n], by = bias[n + 1];
                v1x = cc[0] + bx; v1y = cc[1] + by;
                v2x = cc[2] + bx; v2y = cc[3] + by;
            }
            if constexpr (MODE == 0) {
                float* C = (float*)Cv;
                *(float2*)(C + (size_t)m1 * N + n) = make_float2(v1x, v1y);
                *(float2*)(C + (size_t)m2 * N + n) = make_float2(v2x, v2y);
            } else {
                __half* C = (__half*)Cv;
                int h = n >> 6, d0 = n & 63;
                int b1v = m1 / ntok, t1 = m1 - b1v * ntok;
                int b2v = m2 / ntok, t2 = m2 - b2v * ntok;
                *(__half2*)(C + (((size_t)(b1v * HH + h)) * ntok + t1) * 64 + d0) =
                    __floats2half2_rn(v1x, v1y);
                *(__half2*)(C + (((size_t)(b2v * HH + h)) * ntok + t2) * 64 + d0) =
                    __floats2half2_rn(v2x, v2y);
            }
        }
    }
}

// ---------------- fused attention (cosine baked in; two-pass) -----------------
#define AS 72
#define SQ_OFF 0
#define SK_OFF (128 * AS)
#define SV_OFF (SK_OFF + 2 * 64 * AS)     // pass1 reuses SV as K stages 2,3
#define SP_OFF (SV_OFF + 2 * 64 * AS)
#define SS_OFF (SP_OFF + 128 * AS)
#define ATTN_SMEM (SS_OFF * 2 + 128 * 4)
#define KSTG (64 * AS * 2)                // bytes per K/V stage

__global__ __launch_bounds__(256, 2) void attn_fused(
    const __half* __restrict__ q, const __half* __restrict__ k, const __half* __restrict__ v,
    float* __restrict__ att, __half* __restrict__ ho)
{
    extern __shared__ __half smh[];
    __half* sP = smh + SP_OFF;
    float*  sS = (float*)(smh + SS_OFF);

    const uint32_t sQb = (uint32_t)__cvta_generic_to_shared(smh + SQ_OFF);
    const uint32_t sKb = (uint32_t)__cvta_generic_to_shared(smh + SK_OFF);
    const uint32_t sVb = (uint32_t)__cvta_generic_to_shared(smh + SV_OFF);
    const uint32_t sPb = (uint32_t)__cvta_generic_to_shared(sP);

    const int tid  = threadIdx.x;
    const int wid  = tid >> 5;
    const int lane = tid & 31;
    const int r    = lane >> 2;
    const int cq   = lane & 3;
    const int wm   = wid & 3;
    const int wn   = wid >> 2;

    const int bh = blockIdx.y;
    const int t0 = blockIdx.x * 128;
    const int b  = bh >> 3, h = bh & 7;

    const __half* Qp = q + ((size_t)bh * NTOK + t0) * 64;
    const __half* Kp = k + (size_t)bh * NCTX * 64;
    const __half* Vp = v + (size_t)bh * NCTX * 64;
    float* attp = att + ((size_t)bh * NTOK + t0) * NCTX;

    const int lr  = lane & 7, grp = lane >> 3;
    const int aRO = ((grp & 1) << 3) + lr, aKO = (grp >> 1) << 3;
    const int bRO = ((grp >> 1) << 3) + lr, bKO = (grp & 1) << 3;
    const int vRO = ((grp & 1) << 3) + lr, vDO = (grp >> 1) << 3;

    const int crow = tid >> 3;
    const int cseg = (tid & 7) * 8;

    auto issueQ = [&]() {
#pragma unroll
        for (int i = 0; i < 4; i++) {
            int c = tid + i * 256;
            int row = c >> 3, off = (c & 7) * 8;
            cp16(sQb + (row * AS + off) * 2, Qp + (size_t)row * 64 + off);
        }
    };
    // pass1: 4-stage ring over [SK..SV] space
    auto issueK4 = [&](int stage, int c0) {
#pragma unroll
        for (int i = 0; i < 2; i++) {
            int row = crow + i * 32;
            cp16(sKb + stage * KSTG + (row * AS + cseg) * 2,
                 Kp + (size_t)(c0 + row) * 64 + cseg);
        }
    };
    auto issueV = [&](int buf, int c0) {
#pragma unroll
        for (int i = 0; i < 2; i++) {
            int row = crow + i * 32;
            cp16(sVb + buf * KSTG + (row * AS + cseg) * 2,
                 Vp + (size_t)(c0 + row) * 64 + cseg);
        }
    };

    auto mma1 = [&](int stage, float p[2][4][4]) {
#pragma unroll
        for (int mt = 0; mt < 2; mt++)
#pragma unroll
            for (int nt = 0; nt < 4; nt++)
#pragma unroll
                for (int e = 0; e < 4; e++) p[mt][nt][e] = 0.f;
        const uint32_t kO = sKb + stage * KSTG;
#pragma unroll
        for (int k16 = 0; k16 < 4; k16++) {
            uint32_t af[2][4];
#pragma unroll
            for (int mt = 0; mt < 2; mt++)
                ldsm4(af[mt], sQb + ((wm * 32 + mt * 16 + aRO) * AS + k16 * 16 + aKO) * 2);
            uint32_t bf[4][2];
#pragma unroll
            for (int ntp = 0; ntp < 2; ntp++) {
                uint32_t t[4];
                ldsm4(t, kO + ((wn * 32 + ntp * 16 + bRO) * AS + k16 * 16 + bKO) * 2);
                bf[2 * ntp][0] = t[0]; bf[2 * ntp][1] = t[1];
                bf[2 * ntp + 1][0] = t[2]; bf[2 * ntp + 1][1] = t[3];
            }
#pragma unroll
            for (int mt = 0; mt < 2; mt++)
#pragma unroll
                for (int nt = 0; nt < 4; nt++)
                    mma16(p[mt][nt], af[mt], bf[nt]);
        }
    };

    float rsA[2] = {0.f, 0.f}, rsB[2] = {0.f, 0.f};

    // ============ pass 1: row sums (4-stage K ring, no SMEM epilogue) ========
    issueQ(); issueK4(0, 0); CP_COMMIT();
    issueK4(1, 64); CP_COMMIT();
    issueK4(2, 128); CP_COMMIT();
    for (int ct = 0; ct < 32; ct++) {
        cp_wait<2>(); __syncthreads();
        if (ct + 3 < 32) { issueK4((ct + 3) & 3, (ct + 3) * 64); CP_COMMIT(); }
        float p[2][4][4];
        mma1(ct & 3, p);
#pragma unroll
        for (int mt = 0; mt < 2; mt++) {
#pragma unroll
            for (int nt = 0; nt < 4; nt++) {
                float* cc = p[mt][nt];
                rsA[mt] += exp_c(cc[0]) + exp_c(cc[1]);
                rsB[mt] += exp_c(cc[2]) + exp_c(cc[3]);
            }
        }
    }

    // reduce to sS = 1/sum
#pragma unroll
    for (int mt = 0; mt < 2; mt++) {
        rsA[mt] += __shfl_xor_sync(0xffffffffu, rsA[mt], 1);
        rsA[mt] += __shfl_xor_sync(0xffffffffu, rsA[mt], 2);
        rsB[mt] += __shfl_xor_sync(0xffffffffu, rsB[mt], 1);
        rsB[mt] += __shfl_xor_sync(0xffffffffu, rsB[mt], 2);
    }
    __syncthreads();
    if (wn == 0 && cq == 0) {
#pragma unroll
        for (int mt = 0; mt < 2; mt++) {
            int m1 = wm * 32 + mt * 16 + r;
            sS[m1] = rsA[mt]; sS[m1 + 8] = rsB[mt];
        }
    }
    __syncthreads();
    if (wn == 1 && cq == 0) {
#pragma unroll
        for (int mt = 0; mt < 2; mt++) {
            int m1 = wm * 32 + mt * 16 + r;
            sS[m1] += rsA[mt]; sS[m1 + 8] += rsB[mt];
        }
    }
    __syncthreads();
    if (tid < 128) sS[tid] = 1.0f / sS[tid];
    __syncthreads();

    float invA[2], invB[2];
#pragma unroll
    for (int mt = 0; mt < 2; mt++) {
        int m1 = wm * 32 + mt * 16 + r;
        invA[mt] = sS[m1]; invB[mt] = sS[m1 + 8];
    }

    // ============ pass 2: single att write + AV ==============================
    float av[2][4][4];
#pragma unroll
    for (int mt = 0; mt < 2; mt++)
#pragma unroll
        for (int nt = 0; nt < 4; nt++)
#pragma unroll
            for (int e = 0; e < 4; e++) av[mt][nt][e] = 0.f;

    issueK4(0, 0); issueV(0, 0); CP_COMMIT();

    for (int ct = 0; ct < 32; ct++) {
        const int buf = ct & 1;
        cp_wait<0>(); __syncthreads();
        if (ct + 1 < 32) { issueK4(buf ^ 1, (ct + 1) * 64); issueV(buf ^ 1, (ct + 1) * 64); CP_COMMIT(); }

        float p[2][4][4];
        mma1(buf, p);

#pragma unroll
        for (int mt = 0; mt < 2; mt++) {
            int m1 = wm * 32 + mt * 16 + r, m2 = m1 + 8;
#pragma unroll
            for (int nt = 0; nt < 4; nt++) {
                int nl = wn * 32 + nt * 8 + 2 * cq;
                int ng = ct * 64 + nl;
                float* cc = p[mt][nt];
                float e0 = exp_c(cc[0]);
                float e1 = exp_c(cc[1]);
                float e2 = exp_c(cc[2]);
                float e3 = exp_c(cc[3]);
                __stcs((float2*)(attp + (size_t)m1 * NCTX + ng),
                       make_float2(e0 * invA[mt], e1 * invA[mt]));
                __stcs((float2*)(attp + (size_t)m2 * NCTX + ng),
                       make_float2(e2 * invB[mt], e3 * invB[mt]));
                *(__half2*)&sP[m1 * AS + nl] = __floats2half2_rn(e0, e1);
                *(__half2*)&sP[m2 * AS + nl] = __floats2half2_rn(e2, e3);
            }
        }
        __syncthreads();

        const uint32_t vO = sVb + buf * KSTG;
#pragma unroll
        for (int k16 = 0; k16 < 4; k16++) {
            uint32_t af[2][4];
#pragma unroll
            for (int mt = 0; mt < 2; mt++)
                ldsm4(af[mt], sPb + ((wm * 32 + mt * 16 + aRO) * AS + k16 * 16 + aKO) * 2);
            uint32_t bf[4][2];
#pragma unroll
            for (int ntp = 0; ntp < 2; ntp++) {
                uint32_t t[4];
                ldsm4t(t, vO + ((k16 * 16 + vRO) * AS + wn * 32 + ntp * 16 + vDO) * 2);
                bf[2 * ntp][0] = t[0]; bf[2 * ntp][1] = t[1];
                bf[2 * ntp + 1][0] = t[2]; bf[2 * ntp + 1][1] = t[3];
            }
#pragma unroll
            for (int mt = 0; mt < 2; mt++)
#pragma unroll
                for (int nt = 0; nt < 4; nt++)
                    mma16(av[mt][nt], af[mt], bf[nt]);
        }
    }

    // write AV -> ho (fp16)
#pragma unroll
    for (int mt = 0; mt < 2; mt++) {
        int m1 = wm * 32 + mt * 16 + r, m2 = m1 + 8;
#pragma unroll
        for (int nt = 0; nt < 4; nt++) {
            int d0 = wn * 32 + nt * 8 + 2 * cq;
            float* cc = av[mt][nt];
            *(__half2*)(ho + (((size_t)(b * NTOK + t0 + m1)) * HH + h) * 64 + d0) =
                __floats2half2_rn(cc[0] * invA[mt], cc[1] * invA[mt]);
            *(__half2*)(ho + (((size_t)(b * NTOK + t0 + m2)) * HH + h) * 64 + d0) =
                __floats2half2_rn(cc[2] * invB[mt], cc[3] * invB[mt]);
        }
    }
}

// ---------------- launch -----------------------------------------------------
extern "C" void kernel_launch(void* const* d_in, const int* in_sizes, int n_in,
                              void* d_out, int out_size)
{
    const float* queries = (const float*)d_in[0];
    const float* keys    = (const float*)d_in[1];
    const float* values  = (const float*)d_in[2];
    const float* W_At    = (const float*)d_in[3];
    const float* b_At    = (const float*)d_in[4];
    const float* W_Ac    = (const float*)d_in[5];
    const float* b_Ac    = (const float*)d_in[6];
    const float* W_Bc    = (const float*)d_in[7];
    const float* b_Bc    = (const float*)d_in[8];
    const float* W_R     = (const float*)d_in[9];
    const float* b_R     = (const float*)d_in[10];

    float* out = (float*)d_out;
    float* att = out + OUT_ELEMS;

    __half *xq, *xk, *xv, *wat, *wac, *wbc, *wr, *q, *k, *v, *ho;
    cudaGetSymbolAddress((void**)&xq,  g_xq);
    cudaGetSymbolAddress((void**)&xk,  g_xk);
    cudaGetSymbolAddress((void**)&xv,  g_xv);
    cudaGetSymbolAddress((void**)&wat, g_wat);
    cudaGetSymbolAddress((void**)&wac, g_wac);
    cudaGetSymbolAddress((void**)&wbc, g_wbc);
    cudaGetSymbolAddress((void**)&wr,  g_wr);
    cudaGetSymbolAddress((void**)&q,   g_q);
    cudaGetSymbolAddress((void**)&k,   g_k);
    cudaGetSymbolAddress((void**)&v,   g_v);
    cudaGetSymbolAddress((void**)&ho,  g_ho);

    const int GEMM_SMEM = 8 * GS_A * 2;   // 81920 B, 4-stage
    cudaFuncSetAttribute(gemm_f16<0, false>, cudaFuncAttributeMaxDynamicSharedMemorySize, GEMM_SMEM);
    cudaFuncSetAttribute(gemm_f16<1, false>, cudaFuncAttributeMaxDynamicSharedMemorySize, GEMM_SMEM);
    cudaFuncSetAttribute(gemm_f16<1, true >, cudaFuncAttributeMaxDynamicSharedMemorySize, GEMM_SMEM);
    cudaFuncSetAttribute(attn_fused, cudaFuncAttributeMaxDynamicSharedMemorySize, ATTN_SMEM);

    // all conversions in one launch (9728 blocks; see cvt_all for layout)
    cvt_all<<<9728, 256>>>(queries, keys, values, W_At, W_Ac, W_Bc, W_R);

    // projections: q,k normalized to unit rows; v plain
    gemm_f16<1, true ><<<dim3(4, 32),  256, GEMM_SMEM>>>(xq, wat, b_At, q, B_ * NTOK, HH * DKV, EMBD, NTOK);
    gemm_f16<1, true ><<<dim3(4, 128), 256, GEMM_SMEM>>>(xk, wac, b_Ac, k, B_ * NCTX, HH * DKV, EMBD, NCTX);
    gemm_f16<1, false><<<dim3(4, 128), 256, GEMM_SMEM>>>(xv, wbc, b_Bc, v, B_ * NCTX, HH * DKV, EMBD, NCTX);

    // fused attention (cosine = plain dot of unit vectors)
    attn_fused<<<dim3(4, 64), 256, ATTN_SMEM>>>(q, k, v, att, ho);

    // output projection
    gemm_f16<0, false><<<dim3(4, 32), 256, GEMM_SMEM>>>(ho, wr, b_R, out, B_ * NTOK, EMBD, HH * DKV, 0);
}

// round 14
// speedup vs baseline: 1.5154x; 1.5154x over previous
#include <cuda_runtime.h>
#include <cuda_fp16.h>
#include <math.h>
#include <stdint.h>

#define B_   8
#define NTOK 512
#define NCTX 2048
#define EMBD 512
#define HH   8
#define DKV  64

#define OUT_ELEMS ((size_t)B_ * NTOK * EMBD)

// ---------------- scratch -----------------------------------------------------
__device__ __half g_xq[B_ * NTOK * EMBD];
__device__ __half g_xk[B_ * NCTX * EMBD];
__device__ __half g_xv[B_ * NCTX * EMBD];
__device__ __half g_wat[EMBD * EMBD], g_wac[EMBD * EMBD], g_wbc[EMBD * EMBD], g_wr[EMBD * EMBD];
__device__ __half g_q [B_ * HH * NTOK * DKV];   // unit-norm q-hat
__device__ __half g_k [B_ * HH * NCTX * DKV];   // unit-norm k-hat
__device__ __half g_v [B_ * HH * NCTX * DKV];
__device__ __half g_ho[B_ * NTOK * HH * DKV];

// ---------------- ptx helpers -------------------------------------------------
__device__ __forceinline__ void cp16(uint32_t dst, const void* src) {
    asm volatile("cp.async.cg.shared.global [%0], [%1], 16;" :: "r"(dst), "l"(src));
}
#define CP_COMMIT() asm volatile("cp.async.commit_group;" ::: "memory")
template <int N> __device__ __forceinline__ void cp_wait() {
    asm volatile("cp.async.wait_group %0;" :: "n"(N) : "memory");
}
__device__ __forceinline__ void ldsm4(uint32_t* d, uint32_t addr) {
    asm volatile("ldmatrix.sync.aligned.m8n8.x4.shared.b16 {%0,%1,%2,%3}, [%4];"
        : "=r"(d[0]), "=r"(d[1]), "=r"(d[2]), "=r"(d[3]) : "r"(addr));
}
__device__ __forceinline__ void ldsm4t(uint32_t* d, uint32_t addr) {
    asm volatile("ldmatrix.sync.aligned.m8n8.x4.trans.shared.b16 {%0,%1,%2,%3}, [%4];"
        : "=r"(d[0]), "=r"(d[1]), "=r"(d[2]), "=r"(d[3]) : "r"(addr));
}
__device__ __forceinline__ void mma16(float* c, const uint32_t* a, const uint32_t* b) {
    asm volatile(
        "mma.sync.aligned.m16n8k16.row.col.f32.f16.f16.f32 "
        "{%0,%1,%2,%3}, {%4,%5,%6,%7}, {%8,%9}, {%0,%1,%2,%3};"
        : "+f"(c[0]), "+f"(c[1]), "+f"(c[2]), "+f"(c[3])
        : "r"(a[0]), "r"(a[1]), "r"(a[2]), "r"(a[3]), "r"(b[0]), "r"(b[1]));
}
// exp(x) for |x| <= ~1.0: degree-8 Taylor, 9 FFMA, abs err < 1e-5
__device__ __forceinline__ float exp_c(float x)
{
    float p = 2.48015873e-5f;
    p = fmaf(p, x, 1.98412698e-4f);
    p = fmaf(p, x, 1.38888889e-3f);
    p = fmaf(p, x, 8.33333333e-3f);
    p = fmaf(p, x, 4.16666667e-2f);
    p = fmaf(p, x, 0.16666667f);
    p = fmaf(p, x, 0.5f);
    p = fmaf(p, x, 1.0f);
    p = fmaf(p, x, 1.0f);
    return p;
}

// ---------------- fused fp32 -> fp16 convert (all 7 tensors) ------------------
// 2048 floats per block. q:1024 blocks, k:4096, v:4096, each weight:128 -> 9728.
__global__ __launch_bounds__(256) void cvt_all(
    const float* __restrict__ q, const float* __restrict__ k, const float* __restrict__ v,
    const float* __restrict__ wat, const float* __restrict__ wac,
    const float* __restrict__ wbc, const float* __restrict__ wr)
{
    int bid = blockIdx.x;
    const float* s; __half* d; int off;
    if      (bid < 1024) { s = q;   d = g_xq;  off = bid;        }
    else if (bid < 5120) { s = k;   d = g_xk;  off = bid - 1024; }
    else if (bid < 9216) { s = v;   d = g_xv;  off = bid - 5120; }
    else if (bid < 9344) { s = wat; d = g_wat; off = bid - 9216; }
    else if (bid < 9472) { s = wac; d = g_wac; off = bid - 9344; }
    else if (bid < 9600) { s = wbc; d = g_wbc; off = bid - 9472; }
    else                 { s = wr;  d = g_wr;  off = bid - 9600; }
    size_t i = (size_t)off * 2048 + threadIdx.x * 8;
    float4 a = *(const float4*)(s + i);
    float4 b = *(const float4*)(s + i + 4);
    __half2 h0 = __floats2half2_rn(a.x, a.y), h1 = __floats2half2_rn(a.z, a.w);
    __half2 h2 = __floats2half2_rn(b.x, b.y), h3 = __floats2half2_rn(b.z, b.w);
    uint4 o;
    o.x = *(uint32_t*)&h0; o.y = *(uint32_t*)&h1;
    o.z = *(uint32_t*)&h2; o.w = *(uint32_t*)&h3;
    *(uint4*)(d + i) = o;
}

// ---------------- fp16 NT GEMM (cp.async 3-stage, R8 baseline) ----------------
// MODE 0: float C[m*N+n] = acc + bias
// MODE 1: half head scatter; NORMALIZE: scale each head-row to unit L2 norm
#define SA 40
#define GS_A 5120
template <int MODE, bool NORMALIZE>
__global__ __launch_bounds__(256, 2) void gemm_f16(
    const __half* __restrict__ A, const __half* __restrict__ Bm,
    const float* __restrict__ bias, void* __restrict__ Cv,
    int M, int N, int K, int ntok)
{
    extern __shared__ __half smg[];
    const uint32_t base = (uint32_t)__cvta_generic_to_shared(smg);

    const int tid  = threadIdx.x;
    const int wid  = tid >> 5;
    const int lane = tid & 31;
    const int r    = lane >> 2;
    const int cq   = lane & 3;
    const int wm   = wid & 3;
    const int wn   = wid >> 2;
    const int row0 = blockIdx.y * 128;
    const int col0 = blockIdx.x * 128;

    const int lr  = lane & 7, grp = lane >> 3;
    const int aRO = ((grp & 1) << 3) + lr, aKO = (grp >> 1) << 3;
    const int bRO = ((grp >> 1) << 3) + lr, bKO = (grp & 1) << 3;

    const int crow = tid >> 2;
    const int cseg = (tid & 3) * 8;

    auto issue = [&](int s) {
        int st = s % 3, k0 = s * 32;
        uint32_t dA = base + (st * GS_A) * 2;
        uint32_t dB = base + ((3 + st) * GS_A) * 2;
#pragma unroll
        for (int i = 0; i < 2; i++) {
            int row = crow + i * 64;
            cp16(dA + (row * SA + cseg) * 2, A  + (size_t)(row0 + row) * K + k0 + cseg);
            cp16(dB + (row * SA + cseg) * 2, Bm + (size_t)(col0 + row) * K + k0 + cseg);
        }
    };

    float cr[2][8][4];
#pragma unroll
    for (int mt = 0; mt < 2; mt++)
#pragma unroll
        for (int nt = 0; nt < 8; nt++)
#pragma unroll
            for (int e = 0; e < 4; e++) cr[mt][nt][e] = 0.f;

    const int S = K >> 5;
    issue(0); CP_COMMIT();
    issue(1); CP_COMMIT();

    for (int s = 0; s < S; s++) {
        if (s + 1 < S) cp_wait<1>(); else cp_wait<0>();
        __syncthreads();
        if (s + 2 < S) { issue(s + 2); CP_COMMIT(); }

        const int st = s % 3;
        const uint32_t aO = base + (st * GS_A) * 2;
        const uint32_t bO = base + ((3 + st) * GS_A) * 2;
#pragma unroll
        for (int k16 = 0; k16 < 2; k16++) {
            uint32_t af[2][4];
#pragma unroll
            for (int mt = 0; mt < 2; mt++)
                ldsm4(af[mt], aO + ((wm * 32 + mt * 16 + aRO) * SA + k16 * 16 + aKO) * 2);
            uint32_t bf[8][2];
#pragma unroll
            for (int ntp = 0; ntp < 4; ntp++) {
                uint32_t t[4];
                ldsm4(t, bO + ((wn * 64 + ntp * 16 + bRO) * SA + k16 * 16 + bKO) * 2);
                bf[2 * ntp][0] = t[0]; bf[2 * ntp][1] = t[1];
                bf[2 * ntp + 1][0] = t[2]; bf[2 * ntp + 1][1] = t[3];
            }
#pragma unroll
            for (int mt = 0; mt < 2; mt++)
#pragma unroll
                for (int nt = 0; nt < 8; nt++)
                    mma16(cr[mt][nt], af[mt], bf[nt]);
        }
        __syncthreads();
    }

    // -------- epilogue --------------------------------------------------------
#pragma unroll
    for (int mt = 0; mt < 2; mt++) {
        const int m1 = row0 + wm * 32 + mt * 16 + r;
        const int m2 = m1 + 8;
        float inv1 = 1.f, inv2 = 1.f;

        if (NORMALIZE) {
            float ss1 = 0.f, ss2 = 0.f;
#pragma unroll
            for (int nt = 0; nt < 8; nt++) {
                const int n = col0 + wn * 64 + nt * 8 + 2 * cq;
                float* cc = cr[mt][nt];
                float bx = bias[n], by = bias[n + 1];
                cc[0] += bx; cc[1] += by; cc[2] += bx; cc[3] += by;
                ss1 = fmaf(cc[0], cc[0], fmaf(cc[1], cc[1], ss1));
                ss2 = fmaf(cc[2], cc[2], fmaf(cc[3], cc[3], ss2));
            }
            ss1 += __shfl_xor_sync(0xffffffffu, ss1, 1);
            ss1 += __shfl_xor_sync(0xffffffffu, ss1, 2);
            ss2 += __shfl_xor_sync(0xffffffffu, ss2, 1);
            ss2 += __shfl_xor_sync(0xffffffffu, ss2, 2);
            inv1 = rsqrtf(fmaxf(ss1, 1e-30f));
            inv2 = rsqrtf(fmaxf(ss2, 1e-30f));
        }

#pragma unroll
        for (int nt = 0; nt < 8; nt++) {
            const int n = col0 + wn * 64 + nt * 8 + 2 * cq;
            float* cc = cr[mt][nt];
            float v1x, v1y, v2x, v2y;
            if (NORMALIZE) {
                v1x = cc[0] * inv1; v1y = cc[1] * inv1;
                v2x = cc[2] * inv2; v2y = cc[3] * inv2;
            } else {
                float bx = bias[n], by = bias[n + 1];
                v1x = cc[0] + bx; v1y = cc[1] + by;
                v2x = cc[2] + bx; v2y = cc[3] + by;
            }
            if constexpr (MODE == 0) {
                float* C = (float*)Cv;
                *(float2*)(C + (size_t)m1 * N + n) = make_float2(v1x, v1y);
                *(float2*)(C + (size_t)m2 * N + n) = make_float2(v2x, v2y);
            } else {
                __half* C = (__half*)Cv;
                int h = n >> 6, d0 = n & 63;
                int b1v = m1 / ntok, t1 = m1 - b1v * ntok;
                int b2v = m2 / ntok, t2 = m2 - b2v * ntok;
                *(__half2*)(C + (((size_t)(b1v * HH + h)) * ntok + t1) * 64 + d0) =
                    __floats2half2_rn(v1x, v1y);
                *(__half2*)(C + (((size_t)(b2v * HH + h)) * ntok + t2) * 64 + d0) =
                    __floats2half2_rn(v2x, v2y);
            }
        }
    }
}

// ---------------- fused attention (R8 structure; cosine baked in) -------------
#define AS 72
#define SQ_OFF 0
#define SK_OFF (128 * AS)
#define SV_OFF (SK_OFF + 2 * 64 * AS)
#define SP_OFF (SV_OFF + 2 * 64 * AS)
#define SS_OFF (SP_OFF + 128 * AS)
#define ATTN_SMEM (SS_OFF * 2 + 128 * 4)

__global__ __launch_bounds__(256, 2) void attn_fused(
    const __half* __restrict__ q, const __half* __restrict__ k, const __half* __restrict__ v,
    float* __restrict__ att, __half* __restrict__ ho)
{
    extern __shared__ __half smh[];
    __half* sP = smh + SP_OFF;
    float*  sS = (float*)(smh + SS_OFF);

    const uint32_t sQb = (uint32_t)__cvta_generic_to_shared(smh + SQ_OFF);
    const uint32_t sKb = (uint32_t)__cvta_generic_to_shared(smh + SK_OFF);
    const uint32_t sVb = (uint32_t)__cvta_generic_to_shared(smh + SV_OFF);
    const uint32_t sPb = (uint32_t)__cvta_generic_to_shared(sP);

    const int tid  = threadIdx.x;
    const int wid  = tid >> 5;
    const int lane = tid & 31;
    const int r    = lane >> 2;
    const int cq   = lane & 3;
    const int wm   = wid & 3;
    const int wn   = wid >> 2;

    const int bh = blockIdx.y;
    const int t0 = blockIdx.x * 128;
    const int b  = bh >> 3, h = bh & 7;

    const __half* Qp = q + ((size_t)bh * NTOK + t0) * 64;
    const __half* Kp = k + (size_t)bh * NCTX * 64;
    const __half* Vp = v + (size_t)bh * NCTX * 64;
    float* attp = att + ((size_t)bh * NTOK + t0) * NCTX;

    const int lr  = lane & 7, grp = lane >> 3;
    const int aRO = ((grp & 1) << 3) + lr, aKO = (grp >> 1) << 3;
    const int bRO = ((grp >> 1) << 3) + lr, bKO = (grp & 1) << 3;
    const int vRO = ((grp & 1) << 3) + lr, vDO = (grp >> 1) << 3;

    const int crow = tid >> 3;
    const int cseg = (tid & 7) * 8;

    auto issueQ = [&]() {
#pragma unroll
        for (int i = 0; i < 4; i++) {
            int c = tid + i * 256;
            int row = c >> 3, off = (c & 7) * 8;
            cp16(sQb + (row * AS + off) * 2, Qp + (size_t)row * 64 + off);
        }
    };
    auto issueK = [&](int buf, int c0) {
#pragma unroll
        for (int i = 0; i < 2; i++) {
            int row = crow + i * 32;
            cp16(sKb + (buf * 64 * AS + row * AS + cseg) * 2,
                 Kp + (size_t)(c0 + row) * 64 + cseg);
        }
    };
    auto issueV = [&](int buf, int c0) {
#pragma unroll
        for (int i = 0; i < 2; i++) {
            int row = crow + i * 32;
            cp16(sVb + (buf * 64 * AS + row * AS + cseg) * 2,
                 Vp + (size_t)(c0 + row) * 64 + cseg);
        }
    };

    auto mma1 = [&](int buf, float p[2][4][4]) {
#pragma unroll
        for (int mt = 0; mt < 2; mt++)
#pragma unroll
            for (int nt = 0; nt < 4; nt++)
#pragma unroll
                for (int e = 0; e < 4; e++) p[mt][nt][e] = 0.f;
        const uint32_t kO = sKb + buf * (64 * AS * 2);
#pragma unroll
        for (int k16 = 0; k16 < 4; k16++) {
            uint32_t af[2][4];
#pragma unroll
            for (int mt = 0; mt < 2; mt++)
                ldsm4(af[mt], sQb + ((wm * 32 + mt * 16 + aRO) * AS + k16 * 16 + aKO) * 2);
            uint32_t bf[4][2];
#pragma unroll
            for (int ntp = 0; ntp < 2; ntp++) {
                uint32_t t[4];
                ldsm4(t, kO + ((wn * 32 + ntp * 16 + bRO) * AS + k16 * 16 + bKO) * 2);
                bf[2 * ntp][0] = t[0]; bf[2 * ntp][1] = t[1];
                bf[2 * ntp + 1][0] = t[2]; bf[2 * ntp + 1][1] = t[3];
            }
#pragma unroll
            for (int mt = 0; mt < 2; mt++)
#pragma unroll
                for (int nt = 0; nt < 4; nt++)
                    mma16(p[mt][nt], af[mt], bf[nt]);
        }
    };

    float rsA[2] = {0.f, 0.f}, rsB[2] = {0.f, 0.f};

    // pass 1: row sums
    issueQ(); issueK(0, 0); CP_COMMIT();
    for (int ct = 0; ct < 32; ct++) {
        const int buf = ct & 1;
        cp_wait<0>(); __syncthreads();
        if (ct + 1 < 32) { issueK(buf ^ 1, (ct + 1) * 64); CP_COMMIT(); }
        float p[2][4][4];
        mma1(buf, p);
#pragma unroll
        for (int mt = 0; mt < 2; mt++) {
#pragma unroll
            for (int nt = 0; nt < 4; nt++) {
                float* cc = p[mt][nt];
                rsA[mt] += exp_c(cc[0]) + exp_c(cc[1]);
                rsB[mt] += exp_c(cc[2]) + exp_c(cc[3]);
            }
        }
        __syncthreads();
    }

    // reduce to sS = 1/sum
#pragma unroll
    for (int mt = 0; mt < 2; mt++) {
        rsA[mt] += __shfl_xor_sync(0xffffffffu, rsA[mt], 1);
        rsA[mt] += __shfl_xor_sync(0xffffffffu, rsA[mt], 2);
        rsB[mt] += __shfl_xor_sync(0xffffffffu, rsB[mt], 1);
        rsB[mt] += __shfl_xor_sync(0xffffffffu, rsB[mt], 2);
    }
    if (wn == 0 && cq == 0) {
#pragma unroll
        for (int mt = 0; mt < 2; mt++) {
            int m1 = wm * 32 + mt * 16 + r;
            sS[m1] = rsA[mt]; sS[m1 + 8] = rsB[mt];
        }
    }
    __syncthreads();
    if (wn == 1 && cq == 0) {
#pragma unroll
        for (int mt = 0; mt < 2; mt++) {
            int m1 = wm * 32 + mt * 16 + r;
            sS[m1] += rsA[mt]; sS[m1 + 8] += rsB[mt];
        }
    }
    __syncthreads();
    if (tid < 128) sS[tid] = 1.0f / sS[tid];
    __syncthreads();

    float invA[2], invB[2];
#pragma unroll
    for (int mt = 0; mt < 2; mt++) {
        int m1 = wm * 32 + mt * 16 + r;
        invA[mt] = sS[m1]; invB[mt] = sS[m1 + 8];
    }

    // pass 2: single att write + AV
    float av[2][4][4];
#pragma unroll
    for (int mt = 0; mt < 2; mt++)
#pragma unroll
        for (int nt = 0; nt < 4; nt++)
#pragma unroll
            for (int e = 0; e < 4; e++) av[mt][nt][e] = 0.f;

    issueK(0, 0); issueV(0, 0); CP_COMMIT();

    for (int ct = 0; ct < 32; ct++) {
        const int buf = ct & 1;
        cp_wait<0>(); __syncthreads();
        if (ct + 1 < 32) { issueK(buf ^ 1, (ct + 1) * 64); issueV(buf ^ 1, (ct + 1) * 64); CP_COMMIT(); }

        float p[2][4][4];
        mma1(buf, p);

#pragma unroll
        for (int mt = 0; mt < 2; mt++) {
            int m1 = wm * 32 + mt * 16 + r, m2 = m1 + 8;
#pragma unroll
            for (int nt = 0; nt < 4; nt++) {
                int nl = wn * 32 + nt * 8 + 2 * cq;
                int ng = ct * 64 + nl;
                float* cc = p[mt][nt];
                float e0 = exp_c(cc[0]);
                float e1 = exp_c(cc[1]);
                float e2 = exp_c(cc[2]);
                float e3 = exp_c(cc[3]);
                __stcs((float2*)(attp + (size_t)m1 * NCTX + ng),
                       make_float2(e0 * invA[mt], e1 * invA[mt]));
                __stcs((float2*)(attp + (size_t)m2 * NCTX + ng),
                       make_float2(e2 * invB[mt], e3 * invB[mt]));
                *(__half2*)&sP[m1 * AS + nl] = __floats2half2_rn(e0, e1);
                *(__half2*)&sP[m2 * AS + nl] = __floats2half2_rn(e2, e3);
            }
        }
        __syncthreads();

        const uint32_t vO = sVb + buf * (64 * AS * 2);
#pragma unroll
        for (int k16 = 0; k16 < 4; k16++) {
            uint32_t af[2][4];
#pragma unroll
            for (int mt = 0; mt < 2; mt++)
                ldsm4(af[mt], sPb + ((wm * 32 + mt * 16 + aRO) * AS + k16 * 16 + aKO) * 2);
            uint32_t bf[4][2];
#pragma unroll
            for (int ntp = 0; ntp < 2; ntp++) {
                uint32_t t[4];
                ldsm4t(t, vO + ((k16 * 16 + vRO) * AS + wn * 32 + ntp * 16 + vDO) * 2);
                bf[2 * ntp][0] = t[0]; bf[2 * ntp][1] = t[1];
                bf[2 * ntp + 1][0] = t[2]; bf[2 * ntp + 1][1] = t[3];
            }
#pragma unroll
            for (int mt = 0; mt < 2; mt++)
#pragma unroll
                for (int nt = 0; nt < 4; nt++)
                    mma16(av[mt][nt], af[mt], bf[nt]);
        }
    }

    // write AV -> ho (fp16)
#pragma unroll
    for (int mt = 0; mt < 2; mt++) {
        int m1 = wm * 32 + mt * 16 + r, m2 = m1 + 8;
#pragma unroll
        for (int nt = 0; nt < 4; nt++) {
            int d0 = wn * 32 + nt * 8 + 2 * cq;
            float* cc = av[mt][nt];
            *(__half2*)(ho + (((size_t)(b * NTOK + t0 + m1)) * HH + h) * 64 + d0) =
                __floats2half2_rn(cc[0] * invA[mt], cc[1] * invA[mt]);
            *(__half2*)(ho + (((size_t)(b * NTOK + t0 + m2)) * HH + h) * 64 + d0) =
                __floats2half2_rn(cc[2] * invB[mt], cc[3] * invB[mt]);
        }
    }
}

// ---------------- launch -----------------------------------------------------
extern "C" void kernel_launch(void* const* d_in, const int* in_sizes, int n_in,
                              void* d_out, int out_size)
{
    const float* queries = (const float*)d_in[0];
    const float* keys    = (const float*)d_in[1];
    const float* values  = (const float*)d_in[2];
    const float* W_At    = (const float*)d_in[3];
    const float* b_At    = (const float*)d_in[4];
    const float* W_Ac    = (const float*)d_in[5];
    const float* b_Ac    = (const float*)d_in[6];
    const float* W_Bc    = (const float*)d_in[7];
    const float* b_Bc    = (const float*)d_in[8];
    const float* W_R     = (const float*)d_in[9];
    const float* b_R     = (const float*)d_in[10];

    float* out = (float*)d_out;
    float* att = out + OUT_ELEMS;

    __half *xq, *xk, *xv, *wat, *wac, *wbc, *wr, *q, *k, *v, *ho;
    cudaGetSymbolAddress((void**)&xq,  g_xq);
    cudaGetSymbolAddress((void**)&xk,  g_xk);
    cudaGetSymbolAddress((void**)&xv,  g_xv);
    cudaGetSymbolAddress((void**)&wat, g_wat);
    cudaGetSymbolAddress((void**)&wac, g_wac);
    cudaGetSymbolAddress((void**)&wbc, g_wbc);
    cudaGetSymbolAddress((void**)&wr,  g_wr);
    cudaGetSymbolAddress((void**)&q,   g_q);
    cudaGetSymbolAddress((void**)&k,   g_k);
    cudaGetSymbolAddress((void**)&v,   g_v);
    cudaGetSymbolAddress((void**)&ho,  g_ho);

    const int GEMM_SMEM = 6 * GS_A * 2;   // 61440 B, 3-stage (R8 baseline)
    cudaFuncSetAttribute(gemm_f16<0, false>, cudaFuncAttributeMaxDynamicSharedMemorySize, GEMM_SMEM);
    cudaFuncSetAttribute(gemm_f16<1, false>, cudaFuncAttributeMaxDynamicSharedMemorySize, GEMM_SMEM);
    cudaFuncSetAttribute(gemm_f16<1, true >, cudaFuncAttributeMaxDynamicSharedMemorySize, GEMM_SMEM);
    cudaFuncSetAttribute(attn_fused, cudaFuncAttributeMaxDynamicSharedMemorySize, ATTN_SMEM);

    // all conversions in one launch (9728 blocks)
    cvt_all<<<9728, 256>>>(queries, keys, values, W_At, W_Ac, W_Bc, W_R);

    // projections: q,k normalized to unit rows; v plain
    gemm_f16<1, true ><<<dim3(4, 32),  256, GEMM_SMEM>>>(xq, wat, b_At, q, B_ * NTOK, HH * DKV, EMBD, NTOK);
    gemm_f16<1, true ><<<dim3(4, 128), 256, GEMM_SMEM>>>(xk, wac, b_Ac, k, B_ * NCTX, HH * DKV, EMBD, NCTX);
    gemm_f16<1, false><<<dim3(4, 128), 256, GEMM_SMEM>>>(xv, wbc, b_Bc, v, B_ * NCTX, HH * DKV, EMBD, NCTX);

    // fused attention (cosine = dot of unit vectors)
    attn_fused<<<dim3(4, 64), 256, ATTN_SMEM>>>(q, k, v, att, ho);

    // output projection
    gemm_f16<0, false><<<dim3(4, 32), 256, GEMM_SMEM>>>(ho, wr, b_R, out, B_ * NTOK, EMBD, HH * DKV, 0);
}

// round 16
// speedup vs baseline: 1.6913x; 1.1161x over previous
#include <cuda_runtime.h>
#include <cuda_fp16.h>
#include <math.h>
#include <stdint.h>

#define B_   8
#define NTOK 512
#define NCTX 2048
#define EMBD 512
#define HH   8
#define DKV  64

#define OUT_ELEMS ((size_t)B_ * NTOK * EMBD)

// ---------------- scratch -----------------------------------------------------
__device__ __half g_xq[B_ * NTOK * EMBD];
__device__ __half g_xk[B_ * NCTX * EMBD];
__device__ __half g_xv[B_ * NCTX * EMBD];
__device__ __half g_wat[EMBD * EMBD], g_wac[EMBD * EMBD], g_wbc[EMBD * EMBD], g_wr[EMBD * EMBD];
__device__ __half g_q [B_ * HH * NTOK * DKV];   // unit-norm q-hat
__device__ __half g_k [B_ * HH * NCTX * DKV];   // unit-norm k-hat
__device__ __half g_v [B_ * HH * NCTX * DKV];
__device__ __half g_ho[B_ * NTOK * HH * DKV];
__device__ float  g_bias[4 * EMBD];             // [b_At | b_Ac | b_Bc | unused]

// ---------------- ptx helpers -------------------------------------------------
__device__ __forceinline__ void cp16(uint32_t dst, const void* src) {
    asm volatile("cp.async.cg.shared.global [%0], [%1], 16;" :: "r"(dst), "l"(src));
}
#define CP_COMMIT() asm volatile("cp.async.commit_group;" ::: "memory")
template <int N> __device__ __forceinline__ void cp_wait() {
    asm volatile("cp.async.wait_group %0;" :: "n"(N) : "memory");
}
__device__ __forceinline__ void ldsm4(uint32_t* d, uint32_t addr) {
    asm volatile("ldmatrix.sync.aligned.m8n8.x4.shared.b16 {%0,%1,%2,%3}, [%4];"
        : "=r"(d[0]), "=r"(d[1]), "=r"(d[2]), "=r"(d[3]) : "r"(addr));
}
__device__ __forceinline__ void ldsm4t(uint32_t* d, uint32_t addr) {
    asm volatile("ldmatrix.sync.aligned.m8n8.x4.trans.shared.b16 {%0,%1,%2,%3}, [%4];"
        : "=r"(d[0]), "=r"(d[1]), "=r"(d[2]), "=r"(d[3]) : "r"(addr));
}
__device__ __forceinline__ void mma16(float* c, const uint32_t* a, const uint32_t* b) {
    asm volatile(
        "mma.sync.aligned.m16n8k16.row.col.f32.f16.f16.f32 "
        "{%0,%1,%2,%3}, {%4,%5,%6,%7}, {%8,%9}, {%0,%1,%2,%3};"
        : "+f"(c[0]), "+f"(c[1]), "+f"(c[2]), "+f"(c[3])
        : "r"(a[0]), "r"(a[1]), "r"(a[2]), "r"(a[3]), "r"(b[0]), "r"(b[1]));
}
// exp(x) for |x| <= ~1.0: degree-8 Taylor, 9 FFMA
__device__ __forceinline__ float exp_c(float x)
{
    float p = 2.48015873e-5f;
    p = fmaf(p, x, 1.98412698e-4f);
    p = fmaf(p, x, 1.38888889e-3f);
    p = fmaf(p, x, 8.33333333e-3f);
    p = fmaf(p, x, 4.16666667e-2f);
    p = fmaf(p, x, 0.16666667f);
    p = fmaf(p, x, 0.5f);
    p = fmaf(p, x, 1.0f);
    p = fmaf(p, x, 1.0f);
    return p;
}

// ---------------- fused fp32 -> fp16 convert + bias stage ---------------------
// 2048 floats per block. q:1024, k:4096, v:4096, weights:128 each -> 9728.
__global__ __launch_bounds__(256) void cvt_all(
    const float* __restrict__ q, const float* __restrict__ k, const float* __restrict__ v,
    const float* __restrict__ wat, const float* __restrict__ wac,
    const float* __restrict__ wbc, const float* __restrict__ wr,
    const float* __restrict__ bat, const float* __restrict__ bac,
    const float* __restrict__ bbc)
{
    int bid = blockIdx.x;
    if (bid == 0 && threadIdx.x < 128) {      // stage biases once (512 ea, 4B)
        int t = threadIdx.x;
        ((float4*)g_bias)[t]       = ((const float4*)bat)[t];
        ((float4*)g_bias)[t + 128] = ((const float4*)bac)[t];
        ((float4*)g_bias)[t + 256] = ((const float4*)bbc)[t];
    }
    const float* s; __half* d; int off;
    if      (bid < 1024) { s = q;   d = g_xq;  off = bid;        }
    else if (bid < 5120) { s = k;   d = g_xk;  off = bid - 1024; }
    else if (bid < 9216) { s = v;   d = g_xv;  off = bid - 5120; }
    else if (bid < 9344) { s = wat; d = g_wat; off = bid - 9216; }
    else if (bid < 9472) { s = wac; d = g_wac; off = bid - 9344; }
    else if (bid < 9600) { s = wbc; d = g_wbc; off = bid - 9472; }
    else                 { s = wr;  d = g_wr;  off = bid - 9600; }
    size_t i = (size_t)off * 2048 + threadIdx.x * 8;
    float4 a = *(const float4*)(s + i);
    float4 b = *(const float4*)(s + i + 4);
    __half2 h0 = __floats2half2_rn(a.x, a.y), h1 = __floats2half2_rn(a.z, a.w);
    __half2 h2 = __floats2half2_rn(b.x, b.y), h3 = __floats2half2_rn(b.z, b.w);
    uint4 o;
    o.x = *(uint32_t*)&h0; o.y = *(uint32_t*)&h1;
    o.z = *(uint32_t*)&h2; o.w = *(uint32_t*)&h3;
    *(uint4*)(d + i) = o;
}

// ---------------- unified projection GEMM (z selects q/k/v) -------------------
#define SA 40
#define GS_A 5120
__global__ __launch_bounds__(256, 2) void proj_all()
{
    extern __shared__ __half smg[];
    const uint32_t base = (uint32_t)__cvta_generic_to_shared(smg);

    const int z = blockIdx.z;
    const __half* A;
    const __half* Bm;
    const float*  bias;
    __half* C;
    int M, ntok;
    bool normalize;
    if (z == 0)      { A = g_xq; Bm = g_wat; bias = g_bias;        C = g_q; M = B_ * NTOK; ntok = NTOK; normalize = true;  }
    else if (z == 1) { A = g_xk; Bm = g_wac; bias = g_bias + 512;  C = g_k; M = B_ * NCTX; ntok = NCTX; normalize = true;  }
    else             { A = g_xv; Bm = g_wbc; bias = g_bias + 1024; C = g_v; M = B_ * NCTX; ntok = NCTX; normalize = false; }

    const int row0 = blockIdx.y * 128;
    if (row0 >= M) return;
    const int col0 = blockIdx.x * 128;
    const int K = EMBD, N = HH * DKV;

    const int tid  = threadIdx.x;
    const int wid  = tid >> 5;
    const int lane = tid & 31;
    const int r    = lane >> 2;
    const int cq   = lane & 3;
    const int wm   = wid & 3;
    const int wn   = wid >> 2;

    const int lr  = lane & 7, grp = lane >> 3;
    const int aRO = ((grp & 1) << 3) + lr, aKO = (grp >> 1) << 3;
    const int bRO = ((grp >> 1) << 3) + lr, bKO = (grp & 1) << 3;

    const int crow = tid >> 2;
    const int cseg = (tid & 3) * 8;

    auto issue = [&](int s) {
        int st = s % 3, k0 = s * 32;
        uint32_t dA = base + (st * GS_A) * 2;
        uint32_t dB = base + ((3 + st) * GS_A) * 2;
#pragma unroll
        for (int i = 0; i < 2; i++) {
            int row = crow + i * 64;
            cp16(dA + (row * SA + cseg) * 2, A  + (size_t)(row0 + row) * K + k0 + cseg);
            cp16(dB + (row * SA + cseg) * 2, Bm + (size_t)(col0 + row) * K + k0 + cseg);
        }
    };

    float cr[2][8][4];
#pragma unroll
    for (int mt = 0; mt < 2; mt++)
#pragma unroll
        for (int nt = 0; nt < 8; nt++)
#pragma unroll
            for (int e = 0; e < 4; e++) cr[mt][nt][e] = 0.f;

    const int S = K >> 5;
    issue(0); CP_COMMIT();
    issue(1); CP_COMMIT();

    for (int s = 0; s < S; s++) {
        if (s + 1 < S) cp_wait<1>(); else cp_wait<0>();
        __syncthreads();
        if (s + 2 < S) { issue(s + 2); CP_COMMIT(); }

        const int st = s % 3;
        const uint32_t aO = base + (st * GS_A) * 2;
        const uint32_t bO = base + ((3 + st) * GS_A) * 2;
#pragma unroll
        for (int k16 = 0; k16 < 2; k16++) {
            uint32_t af[2][4];
#pragma unroll
            for (int mt = 0; mt < 2; mt++)
                ldsm4(af[mt], aO + ((wm * 32 + mt * 16 + aRO) * SA + k16 * 16 + aKO) * 2);
            uint32_t bf[8][2];
#pragma unroll
            for (int ntp = 0; ntp < 4; ntp++) {
                uint32_t t[4];
                ldsm4(t, bO + ((wn * 64 + ntp * 16 + bRO) * SA + k16 * 16 + bKO) * 2);
                bf[2 * ntp][0] = t[0]; bf[2 * ntp][1] = t[1];
                bf[2 * ntp + 1][0] = t[2]; bf[2 * ntp + 1][1] = t[3];
            }
#pragma unroll
            for (int mt = 0; mt < 2; mt++)
#pragma unroll
                for (int nt = 0; nt < 8; nt++)
                    mma16(cr[mt][nt], af[mt], bf[nt]);
        }
        __syncthreads();
    }

    // epilogue: bias; optional per-head-row unit normalization; head scatter
#pragma unroll
    for (int mt = 0; mt < 2; mt++) {
        const int m1 = row0 + wm * 32 + mt * 16 + r;
        const int m2 = m1 + 8;
        float inv1 = 1.f, inv2 = 1.f;

        float ss1 = 0.f, ss2 = 0.f;
#pragma unroll
        for (int nt = 0; nt < 8; nt++) {
            const int n = col0 + wn * 64 + nt * 8 + 2 * cq;
            float* cc = cr[mt][nt];
            float bx = bias[n], by = bias[n + 1];
            cc[0] += bx; cc[1] += by; cc[2] += bx; cc[3] += by;
            ss1 = fmaf(cc[0], cc[0], fmaf(cc[1], cc[1], ss1));
            ss2 = fmaf(cc[2], cc[2], fmaf(cc[3], cc[3], ss2));
        }
        if (normalize) {
            ss1 += __shfl_xor_sync(0xffffffffu, ss1, 1);
            ss1 += __shfl_xor_sync(0xffffffffu, ss1, 2);
            ss2 += __shfl_xor_sync(0xffffffffu, ss2, 1);
            ss2 += __shfl_xor_sync(0xffffffffu, ss2, 2);
            inv1 = rsqrtf(fmaxf(ss1, 1e-30f));
            inv2 = rsqrtf(fmaxf(ss2, 1e-30f));
        }

#pragma unroll
        for (int nt = 0; nt < 8; nt++) {
            const int n = col0 + wn * 64 + nt * 8 + 2 * cq;
            float* cc = cr[mt][nt];
            float v1x = cc[0] * inv1, v1y = cc[1] * inv1;
            float v2x = cc[2] * inv2, v2y = cc[3] * inv2;
            int h = n >> 6, d0 = n & 63;
            int b1v = m1 / ntok, t1 = m1 - b1v * ntok;
            int b2v = m2 / ntok, t2 = m2 - b2v * ntok;
            *(__half2*)(C + (((size_t)(b1v * HH + h)) * ntok + t1) * 64 + d0) =
                __floats2half2_rn(v1x, v1y);
            *(__half2*)(C + (((size_t)(b2v * HH + h)) * ntok + t2) * 64 + d0) =
                __floats2half2_rn(v2x, v2y);
        }
    }
}

// ---------------- out projection (fp16 NT GEMM, float out) --------------------
__global__ __launch_bounds__(256, 2) void gemm_out(
    const __half* __restrict__ A, const __half* __restrict__ Bm,
    const float* __restrict__ bias, float* __restrict__ C,
    int M, int N, int K)
{
    extern __shared__ __half smg[];
    const uint32_t base = (uint32_t)__cvta_generic_to_shared(smg);

    const int tid  = threadIdx.x;
    const int wid  = tid >> 5;
    const int lane = tid & 31;
    const int r    = lane >> 2;
    const int cq   = lane & 3;
    const int wm   = wid & 3;
    const int wn   = wid >> 2;
    const int row0 = blockIdx.y * 128;
    const int col0 = blockIdx.x * 128;

    const int lr  = lane & 7, grp = lane >> 3;
    const int aRO = ((grp & 1) << 3) + lr, aKO = (grp >> 1) << 3;
    const int bRO = ((grp >> 1) << 3) + lr, bKO = (grp & 1) << 3;

    const int crow = tid >> 2;
    const int cseg = (tid & 3) * 8;

    auto issue = [&](int s) {
        int st = s % 3, k0 = s * 32;
        uint32_t dA = base + (st * GS_A) * 2;
        uint32_t dB = base + ((3 + st) * GS_A) * 2;
#pragma unroll
        for (int i = 0; i < 2; i++) {
            int row = crow + i * 64;
            cp16(dA + (row * SA + cseg) * 2, A  + (size_t)(row0 + row) * K + k0 + cseg);
            cp16(dB + (row * SA + cseg) * 2, Bm + (size_t)(col0 + row) * K + k0 + cseg);
        }
    };

    float cr[2][8][4];
#pragma unroll
    for (int mt = 0; mt < 2; mt++)
#pragma unroll
        for (int nt = 0; nt < 8; nt++)
#pragma unroll
            for (int e = 0; e < 4; e++) cr[mt][nt][e] = 0.f;

    const int S = K >> 5;
    issue(0); CP_COMMIT();
    issue(1); CP_COMMIT();

    for (int s = 0; s < S; s++) {
        if (s + 1 < S) cp_wait<1>(); else cp_wait<0>();
        __syncthreads();
        if (s + 2 < S) { issue(s + 2); CP_COMMIT(); }

        const int st = s % 3;
        const uint32_t aO = base + (st * GS_A) * 2;
        const uint32_t bO = base + ((3 + st) * GS_A) * 2;
#pragma unroll
        for (int k16 = 0; k16 < 2; k16++) {
            uint32_t af[2][4];
#pragma unroll
            for (int mt = 0; mt < 2; mt++)
                ldsm4(af[mt], aO + ((wm * 32 + mt * 16 + aRO) * SA + k16 * 16 + aKO) * 2);
            uint32_t bf[8][2];
#pragma unroll
            for (int ntp = 0; ntp < 4; ntp++) {
                uint32_t t[4];
                ldsm4(t, bO + ((wn * 64 + ntp * 16 + bRO) * SA + k16 * 16 + bKO) * 2);
                bf[2 * ntp][0] = t[0]; bf[2 * ntp][1] = t[1];
                bf[2 * ntp + 1][0] = t[2]; bf[2 * ntp + 1][1] = t[3];
            }
#pragma unroll
            for (int mt = 0; mt < 2; mt++)
#pragma unroll
                for (int nt = 0; nt < 8; nt++)
                    mma16(cr[mt][nt], af[mt], bf[nt]);
        }
        __syncthreads();
    }

#pragma unroll
    for (int mt = 0; mt < 2; mt++) {
        const int m1 = row0 + wm * 32 + mt * 16 + r;
        const int m2 = m1 + 8;
#pragma unroll
        for (int nt = 0; nt < 8; nt++) {
            const int n = col0 + wn * 64 + nt * 8 + 2 * cq;
            float* cc = cr[mt][nt];
            float bx = bias[n], by = bias[n + 1];
            *(float2*)(C + (size_t)m1 * N + n) = make_float2(cc[0] + bx, cc[1] + by);
            *(float2*)(C + (size_t)m2 * N + n) = make_float2(cc[2] + bx, cc[3] + by);
        }
    }
}

// ---------------- fused attention (pass1 4-ring; pass2 as R14) ----------------
#define AS 72
#define SQ_OFF 0
#define SK_OFF (128 * AS)
#define SV_OFF (SK_OFF + 2 * 64 * AS)     // pass1 uses SK..SV as 4 K stages
#define SP_OFF (SV_OFF + 2 * 64 * AS)
#define SS_OFF (SP_OFF + 128 * AS)
#define ATTN_SMEM (SS_OFF * 2 + 128 * 4)
#define KSTG (64 * AS * 2)

__global__ __launch_bounds__(256, 2) void attn_fused(
    const __half* __restrict__ q, const __half* __restrict__ k, const __half* __restrict__ v,
    float* __restrict__ att, __half* __restrict__ ho)
{
    extern __shared__ __half smh[];
    __half* sP = smh + SP_OFF;
    float*  sS = (float*)(smh + SS_OFF);

    const uint32_t sQb = (uint32_t)__cvta_generic_to_shared(smh + SQ_OFF);
    const uint32_t sKb = (uint32_t)__cvta_generic_to_shared(smh + SK_OFF);
    const uint32_t sVb = (uint32_t)__cvta_generic_to_shared(smh + SV_OFF);
    const uint32_t sPb = (uint32_t)__cvta_generic_to_shared(sP);

    const int tid  = threadIdx.x;
    const int wid  = tid >> 5;
    const int lane = tid & 31;
    const int r    = lane >> 2;
    const int cq   = lane & 3;
    const int wm   = wid & 3;
    const int wn   = wid >> 2;

    const int bh = blockIdx.y;
    const int t0 = blockIdx.x * 128;
    const int b  = bh >> 3, h = bh & 7;

    const __half* Qp = q + ((size_t)bh * NTOK + t0) * 64;
    const __half* Kp = k + (size_t)bh * NCTX * 64;
    const __half* Vp = v + (size_t)bh * NCTX * 64;
    float* attp = att + ((size_t)bh * NTOK + t0) * NCTX;

    const int lr  = lane & 7, grp = lane >> 3;
    const int aRO = ((grp & 1) << 3) + lr, aKO = (grp >> 1) << 3;
    const int bRO = ((grp >> 1) << 3) + lr, bKO = (grp & 1) << 3;
    const int vRO = ((grp & 1) << 3) + lr, vDO = (grp >> 1) << 3;

    const int crow = tid >> 3;
    const int cseg = (tid & 7) * 8;

    auto issueQ = [&]() {
#pragma unroll
        for (int i = 0; i < 4; i++) {
            int c = tid + i * 256;
            int row = c >> 3, off = (c & 7) * 8;
            cp16(sQb + (row * AS + off) * 2, Qp + (size_t)row * 64 + off);
        }
    };
    auto issueKst = [&](int stage, int c0) {    // stage 0..3 over SK..SV space
#pragma unroll
        for (int i = 0; i < 2; i++) {
            int row = crow + i * 32;
            cp16(sKb + stage * KSTG + (row * AS + cseg) * 2,
                 Kp + (size_t)(c0 + row) * 64 + cseg);
        }
    };
    auto issueV = [&](int buf, int c0) {
#pragma unroll
        for (int i = 0; i < 2; i++) {
            int row = crow + i * 32;
            cp16(sVb + buf * KSTG + (row * AS + cseg) * 2,
                 Vp + (size_t)(c0 + row) * 64 + cseg);
        }
    };

    auto mma1 = [&](int stage, float p[2][4][4]) {
#pragma unroll
        for (int mt = 0; mt < 2; mt++)
#pragma unroll
            for (int nt = 0; nt < 4; nt++)
#pragma unroll
                for (int e = 0; e < 4; e++) p[mt][nt][e] = 0.f;
        const uint32_t kO = sKb + stage * KSTG;
#pragma unroll
        for (int k16 = 0; k16 < 4; k16++) {
            uint32_t af[2][4];
#pragma unroll
            for (int mt = 0; mt < 2; mt++)
                ldsm4(af[mt], sQb + ((wm * 32 + mt * 16 + aRO) * AS + k16 * 16 + aKO) * 2);
            uint32_t bf[4][2];
#pragma unroll
            for (int ntp = 0; ntp < 2; ntp++) {
                uint32_t t[4];
                ldsm4(t, kO + ((wn * 32 + ntp * 16 + bRO) * AS + k16 * 16 + bKO) * 2);
                bf[2 * ntp][0] = t[0]; bf[2 * ntp][1] = t[1];
                bf[2 * ntp + 1][0] = t[2]; bf[2 * ntp + 1][1] = t[3];
            }
#pragma unroll
            for (int mt = 0; mt < 2; mt++)
#pragma unroll
                for (int nt = 0; nt < 4; nt++)
                    mma16(p[mt][nt], af[mt], bf[nt]);
        }
    };

    float rsA[2] = {0.f, 0.f}, rsB[2] = {0.f, 0.f};

    // ============ pass 1: row sums (4-stage K ring; single barrier/iter) =====
    issueQ(); issueKst(0, 0); CP_COMMIT();
    issueKst(1, 64); CP_COMMIT();
    issueKst(2, 128); CP_COMMIT();
    for (int ct = 0; ct < 32; ct++) {
        cp_wait<2>(); __syncthreads();
        if (ct + 3 < 32) { issueKst((ct + 3) & 3, (ct + 3) * 64); CP_COMMIT(); }
        float p[2][4][4];
        mma1(ct & 3, p);
#pragma unroll
        for (int mt = 0; mt < 2; mt++) {
#pragma unroll
            for (int nt = 0; nt < 4; nt++) {
                float* cc = p[mt][nt];
                rsA[mt] += exp_c(cc[0]) + exp_c(cc[1]);
                rsB[mt] += exp_c(cc[2]) + exp_c(cc[3]);
            }
        }
    }

    // reduce to sS = 1/sum
#pragma unroll
    for (int mt = 0; mt < 2; mt++) {
        rsA[mt] += __shfl_xor_sync(0xffffffffu, rsA[mt], 1);
        rsA[mt] += __shfl_xor_sync(0xffffffffu, rsA[mt], 2);
        rsB[mt] += __shfl_xor_sync(0xffffffffu, rsB[mt], 1);
        rsB[mt] += __shfl_xor_sync(0xffffffffu, rsB[mt], 2);
    }
    __syncthreads();
    if (wn == 0 && cq == 0) {
#pragma unroll
        for (int mt = 0; mt < 2; mt++) {
            int m1 = wm * 32 + mt * 16 + r;
            sS[m1] = rsA[mt]; sS[m1 + 8] = rsB[mt];
        }
    }
    __syncthreads();
    if (wn == 1 && cq == 0) {
#pragma unroll
        for (int mt = 0; mt < 2; mt++) {
            int m1 = wm * 32 + mt * 16 + r;
            sS[m1] += rsA[mt]; sS[m1 + 8] += rsB[mt];
        }
    }
    __syncthreads();
    if (tid < 128) sS[tid] = 1.0f / sS[tid];
    __syncthreads();

    float invA[2], invB[2];
#pragma unroll
    for (int mt = 0; mt < 2; mt++) {
        int m1 = wm * 32 + mt * 16 + r;
        invA[mt] = sS[m1]; invB[mt] = sS[m1 + 8];
    }

    // ============ pass 2: single att write + AV (R14 unchanged) ==============
    float av[2][4][4];
#pragma unroll
    for (int mt = 0; mt < 2; mt++)
#pragma unroll
        for (int nt = 0; nt < 4; nt++)
#pragma unroll
            for (int e = 0; e < 4; e++) av[mt][nt][e] = 0.f;

    issueKst(0, 0); issueV(0, 0); CP_COMMIT();

    for (int ct = 0; ct < 32; ct++) {
        const int buf = ct & 1;
        cp_wait<0>(); __syncthreads();
        if (ct + 1 < 32) { issueKst(buf ^ 1, (ct + 1) * 64); issueV(buf ^ 1, (ct + 1) * 64); CP_COMMIT(); }

        float p[2][4][4];
        mma1(buf, p);

#pragma unroll
        for (int mt = 0; mt < 2; mt++) {
            int m1 = wm * 32 + mt * 16 + r, m2 = m1 + 8;
#pragma unroll
            for (int nt = 0; nt < 4; nt++) {
                int nl = wn * 32 + nt * 8 + 2 * cq;
                int ng = ct * 64 + nl;
                float* cc = p[mt][nt];
                float e0 = exp_c(cc[0]);
                float e1 = exp_c(cc[1]);
                float e2 = exp_c(cc[2]);
                float e3 = exp_c(cc[3]);
                __stcs((float2*)(attp + (size_t)m1 * NCTX + ng),
                       make_float2(e0 * invA[mt], e1 * invA[mt]));
                __stcs((float2*)(attp + (size_t)m2 * NCTX + ng),
                       make_float2(e2 * invB[mt], e3 * invB[mt]));
                *(__half2*)&sP[m1 * AS + nl] = __floats2half2_rn(e0, e1);
                *(__half2*)&sP[m2 * AS + nl] = __floats2half2_rn(e2, e3);
            }
        }
        __syncthreads();

        const uint32_t vO = sVb + buf * KSTG;
#pragma unroll
        for (int k16 = 0; k16 < 4; k16++) {
            uint32_t af[2][4];
#pragma unroll
            for (int mt = 0; mt < 2; mt++)
                ldsm4(af[mt], sPb + ((wm * 32 + mt * 16 + aRO) * AS + k16 * 16 + aKO) * 2);
            uint32_t bf[4][2];
#pragma unroll
            for (int ntp = 0; ntp < 2; ntp++) {
                uint32_t t[4];
                ldsm4t(t, vO + ((k16 * 16 + vRO) * AS + wn * 32 + ntp * 16 + vDO) * 2);
                bf[2 * ntp][0] = t[0]; bf[2 * ntp][1] = t[1];
                bf[2 * ntp + 1][0] = t[2]; bf[2 * ntp + 1][1] = t[3];
            }
#pragma unroll
            for (int mt = 0; mt < 2; mt++)
#pragma unroll
                for (int nt = 0; nt < 4; nt++)
                    mma16(av[mt][nt], af[mt], bf[nt]);
        }
    }

    // write AV -> ho (fp16)
#pragma unroll
    for (int mt = 0; mt < 2; mt++) {
        int m1 = wm * 32 + mt * 16 + r, m2 = m1 + 8;
#pragma unroll
        for (int nt = 0; nt < 4; nt++) {
            int d0 = wn * 32 + nt * 8 + 2 * cq;
            float* cc = av[mt][nt];
            *(__half2*)(ho + (((size_t)(b * NTOK + t0 + m1)) * HH + h) * 64 + d0) =
                __floats2half2_rn(cc[0] * invA[mt], cc[1] * invA[mt]);
            *(__half2*)(ho + (((size_t)(b * NTOK + t0 + m2)) * HH + h) * 64 + d0) =
                __floats2half2_rn(cc[2] * invB[mt], cc[3] * invB[mt]);
        }
    }
}

// ---------------- launch -----------------------------------------------------
extern "C" void kernel_launch(void* const* d_in, const int* in_sizes, int n_in,
                              void* d_out, int out_size)
{
    const float* queries = (const float*)d_in[0];
    const float* keys    = (const float*)d_in[1];
    const float* values  = (const float*)d_in[2];
    const float* W_At    = (const float*)d_in[3];
    const float* b_At    = (const float*)d_in[4];
    const float* W_Ac    = (const float*)d_in[5];
    const float* b_Ac    = (const float*)d_in[6];
    const float* W_Bc    = (const float*)d_in[7];
    const float* b_Bc    = (const float*)d_in[8];
    const float* W_R     = (const float*)d_in[9];
    const float* b_R     = (const float*)d_in[10];

    float* out = (float*)d_out;
    float* att = out + OUT_ELEMS;

    __half *q, *k, *v, *ho, *wr;
    cudaGetSymbolAddress((void**)&q,  g_q);
    cudaGetSymbolAddress((void**)&k,  g_k);
    cudaGetSymbolAddress((void**)&v,  g_v);
    cudaGetSymbolAddress((void**)&ho, g_ho);
    cudaGetSymbolAddress((void**)&wr, g_wr);

    const int GEMM_SMEM = 6 * GS_A * 2;   // 61440 B, 3-stage
    cudaFuncSetAttribute(proj_all,  cudaFuncAttributeMaxDynamicSharedMemorySize, GEMM_SMEM);
    cudaFuncSetAttribute(gemm_out,  cudaFuncAttributeMaxDynamicSharedMemorySize, GEMM_SMEM);
    cudaFuncSetAttribute(attn_fused, cudaFuncAttributeMaxDynamicSharedMemorySize, ATTN_SMEM);

    // conversions + bias staging, one launch
    cvt_all<<<9728, 256>>>(queries, keys, values, W_At, W_Ac, W_Bc, W_R,
                           b_At, b_Ac, b_Bc);

    // all three projections, one launch (z: 0=q[norm],1=k[norm],2=v)
    proj_all<<<dim3(4, 128, 3), 256, GEMM_SMEM>>>();

    // fused attention (cosine = dot of unit vectors)
    attn_fused<<<dim3(4, 64), 256, ATTN_SMEM>>>(q, k, v, att, ho);

    // output projection
    gemm_out<<<dim3(4, 32), 256, GEMM_SMEM>>>(ho, wr, b_R, out, B_ * NTOK, EMBD, HH * DKV);
}